// round 14
// baseline (speedup 1.0000x reference)
#include <cuda_runtime.h>
#include <stdint.h>

// ============================================================================
// Exact VQ argmin via packed fp32x2 FMA (SASS FFMA2, 2 MAC/instr).
// R14 = R13 sweep (untouched, at fma-issue floor) + higher-parallelism small
//       kernels: prep 16 codes/CTA (grid 256), gather GT=16 (grid 1024).
// ============================================================================

#define NTOK   16384
#define DIM    256
#define HW     1024
#define KCODES 4096
#define MTILE  112
#define NCTA   147              // ceil(16384/112)
#define CTILE  256              // codes per tile
#define DC     32               // dims per chunk
#define NCHUNK ((KCODES / CTILE) * (DIM / DC))   // 16 * 8 = 128
#define BSTG   32768            // one B stage: 32 d x 1024B

// sweep smem (bytes)
#define SM_A    0                 // 256 d x 112 tok x 4B = 114688
#define SM_B    114688            // 3 x 32768 = 98304
#define SM_Q    212992            // csqh 4096 f32 = 16384
#define SM_BEST 229376            // 112 u64 (+pad)
#define SM_TOT  230400

// gather
#define GT      16                // tokens per gather CTA
#define GROW    257               // padded row stride (floats)
#define GSM_TOT (GT * GROW * 4 + 256)

// prep
#define PC      16                // codes per prep CTA

__device__ float g_cbT[DIM * KCODES];   // [d][code]
__device__ float g_csqh[KCODES];        // -0.5*||c||^2
__device__ int   g_idx[NTOK];

typedef unsigned long long u64;
__device__ __forceinline__ uint32_t smem_u32(const void* p) {
    uint32_t a;
    asm("{ .reg .u64 t; cvta.to.shared.u64 t, %1; cvt.u32.u64 %0, t; }" : "=r"(a) : "l"(p));
    return a;
}
__device__ __forceinline__ unsigned ford(float f) {
    unsigned u = __float_as_uint(f);
    return (u & 0x80000000u) ? ~u : (u | 0x80000000u);
}
__device__ __forceinline__ u64 pack2(float v) {
    u64 r; unsigned b = __float_as_uint(v);
    asm("mov.b64 %0, {%1, %1};" : "=l"(r) : "r"(b));
    return r;
}
__device__ __forceinline__ void fma2(u64& acc, u64 a, u64 b) {
    asm("fma.rn.f32x2 %0, %1, %2, %0;" : "+l"(acc) : "l"(a), "l"(b));
}
__device__ __forceinline__ void lds_v2u64(u64& r0, u64& r1, uint32_t a) {
    asm volatile("ld.shared.v2.u64 {%0,%1}, [%2];" : "=l"(r0), "=l"(r1) : "r"(a));
}
#define CP16(d, s)  asm volatile("cp.async.cg.shared.global [%0], [%1], 16;" :: "r"(d), "l"(s))
#define CPCOMMIT()  asm volatile("cp.async.commit_group;" ::: "memory")
#define CPWAIT1()   asm volatile("cp.async.wait_group 1;" ::: "memory")
#define CPWAIT0()   asm volatile("cp.async.wait_group 0;" ::: "memory")

// ---------------- fused prep: transpose + csqh, 16 codes/CTA ----------------
__global__ __launch_bounds__(256) void prep_kernel(const float* __restrict__ cb) {
    __shared__ float t[PC * GROW];            // [code][d], stride 257
    const int tid  = threadIdx.x;
    const int code = tid >> 4;                // 0..15
    const int seg  = tid & 15;                // 16-dim segment
    const int c0   = blockIdx.x * PC;

    const float* row = cb + (size_t)(c0 + code) * DIM + seg * 16;
    float sq = 0.f;
#pragma unroll
    for (int i = 0; i < 4; i++) {
        float4 v = reinterpret_cast<const float4*>(row)[i];
        sq = fmaf(v.x, v.x, sq); sq = fmaf(v.y, v.y, sq);
        sq = fmaf(v.z, v.z, sq); sq = fmaf(v.w, v.w, sq);
        const int d = seg * 16 + i * 4;
        t[code * GROW + d + 0] = v.x;
        t[code * GROW + d + 1] = v.y;
        t[code * GROW + d + 2] = v.z;
        t[code * GROW + d + 3] = v.w;
    }
    // 16-lane sumsq reduction (seg 0..15 of same code are contiguous lanes)
#pragma unroll
    for (int o = 8; o > 0; o >>= 1) sq += __shfl_xor_sync(0xFFFFFFFFu, sq, o);
    if (seg == 0) g_csqh[c0 + code] = -0.5f * sq;
    __syncthreads();

    // transposed write: per iter 16 d-rows x 16 codes
#pragma unroll
    for (int k = 0; k < 16; k++) {
        const int d  = k * 16 + (tid >> 4);
        const int cc = tid & 15;
        g_cbT[(size_t)d * KCODES + c0 + cc] = t[cc * GROW + d];
    }
}

// B chunk prefetch: chunk index cc -> stage cc%3
__device__ __forceinline__ void prefetch_chunk(uint32_t sb, int cc, int tid) {
    const int ct = cc >> 3, dcc = cc & 7;
    const char* src = reinterpret_cast<const char*>(
        g_cbT + (size_t)(dcc * DC) * KCODES + ct * CTILE);
    const uint32_t dst = sb + SM_B + (cc % 3) * BSTG;
#pragma unroll
    for (int k = 0; k < 8; k++) {
        int s = tid + k * 256;                 // 2048 x 16B
        int r = s >> 6, c = s & 63;
        CP16(dst + r * 1024 + c * 16, src + (size_t)r * (KCODES * 4) + c * 16);
    }
    CPCOMMIT();
}

// ---------------- main sweep (unchanged from R13) ----------------
__global__ __launch_bounds__(256, 1) void sweep_kernel(const float* __restrict__ x) {
    extern __shared__ char sm[];
    float* Af     = reinterpret_cast<float*>(sm + SM_A);   // [d][112]
    float* csqh_s = reinterpret_cast<float*>(sm + SM_Q);
    u64*   sbest  = reinterpret_cast<u64*>(sm + SM_BEST);
    const uint32_t sb = smem_u32(sm);

    const int tid = threadIdx.x;
    const int tx  = tid & 15;       // code group (codes tx*4 + s*64 + q*2 .. +1)
    const int ty  = tid >> 4;       // token slot: tokens ty + 16*m, m<7
    const int n0  = blockIdx.x * MTILE;

    // ---- A fill: one d-row per thread, 28 x 16B cp.async, batch-split ----
    {
        const int pos0 = n0 & (HW - 1);
        const int b0   = n0 >> 10;
        const int len1 = min(MTILE, HW - pos0);          // multiple of 16
        const int d    = tid;
        const uint32_t dst = sb + SM_A + d * (MTILE * 4);
#pragma unroll
        for (int c = 0; c < 28; c++) {
            const int col0 = c * 4;                      // 4 tokens = 16 bytes
            if (col0 < len1) {
                const float* src = x + ((size_t)b0 * DIM + d) * HW + pos0 + col0;
                CP16(dst + col0 * 4, src);
            } else if (b0 + 1 < 16) {
                const float* src = x + ((size_t)(b0 + 1) * DIM + d) * HW + (col0 - len1);
                CP16(dst + col0 * 4, src);
            }
        }
        CPCOMMIT();
    }
    for (int i = tid; i < KCODES; i += 256) csqh_s[i] = g_csqh[i];
    if (tid < MTILE) sbest[tid] = 0ull;
    // ---- B prologue: chunks 0 and 1 ----
    prefetch_chunk(sb, 0, tid);
    prefetch_chunk(sb, 1, tid);

    float bestv[7];
    int   bestc[7];
#pragma unroll
    for (int i = 0; i < 7; i++) { bestv[i] = -3.4e38f; bestc[i] = 0; }

    u64 acc[7][8];

    for (int cidx = 0; cidx < NCHUNK; cidx++) {
        const int ct  = cidx >> 3;
        const int dcc = cidx & 7;

        // wait for chunk cidx (leave next in flight); single barrier makes
        // chunk cidx visible AND proves all warps finished cidx-1, whose
        // stage (cidx+2)%3 we are about to overwrite.
        if (cidx + 1 < NCHUNK) CPWAIT1(); else CPWAIT0();
        __syncthreads();
        if (cidx + 2 < NCHUNK) prefetch_chunk(sb, cidx + 2, tid);

        // acc init at tile start: -0.5*||c||^2 pairs (codes tx*4 + s*64 + q*2)
        if (dcc == 0) {
            const int qb = ct * CTILE + tx * 4;
            u64 k8[8];
#pragma unroll
            for (int s = 0; s < 4; s++) {
                k8[s * 2]     = *reinterpret_cast<const u64*>(csqh_s + qb + s * 64);
                k8[s * 2 + 1] = *reinterpret_cast<const u64*>(csqh_s + qb + s * 64 + 2);
            }
#pragma unroll
            for (int i = 0; i < 7; i++)
#pragma unroll
                for (int j = 0; j < 8; j++) acc[i][j] = k8[j];
        }

        // ---- compute 32 d-steps ----
        const float*   Abase = Af + dcc * DC * MTILE + ty;
        const uint32_t Bbase = sb + SM_B + (cidx % 3) * BSTG + tx * 16;
#pragma unroll 4
        for (int k = 0; k < DC; k++) {
            u64 pa[7];
#pragma unroll
            for (int m = 0; m < 7; m++)
                pa[m] = pack2(Abase[k * MTILE + 16 * m]);
            u64 bb[8];
#pragma unroll
            for (int s = 0; s < 4; s++)
                lds_v2u64(bb[s * 2], bb[s * 2 + 1], Bbase + k * 1024 + s * 256);
#pragma unroll
            for (int i = 0; i < 7; i++)
#pragma unroll
                for (int j = 0; j < 8; j++)
                    fma2(acc[i][j], pa[i], bb[j]);
        }

        // ---- tile epilogue: running argmax ----
        if (dcc == 7) {
            const int cb0 = ct * CTILE + tx * 4;
#pragma unroll
            for (int i = 0; i < 7; i++)
#pragma unroll
                for (int s = 0; s < 4; s++)
#pragma unroll
                    for (int q = 0; q < 2; q++) {
                        unsigned lo, hi;
                        asm("mov.b64 {%0,%1}, %2;" : "=r"(lo), "=r"(hi) : "l"(acc[i][s * 2 + q]));
                        float v0 = __uint_as_float(lo), v1 = __uint_as_float(hi);
                        int c = cb0 + s * 64 + q * 2;
                        if (v0 > bestv[i]) { bestv[i] = v0; bestc[i] = c; }
                        if (v1 > bestv[i]) { bestv[i] = v1; bestc[i] = c + 1; }
                    }
        }
    }

    // ---- cross-thread reduction: max value, then min code ----
#pragma unroll
    for (int i = 0; i < 7; i++) {
        u64 key = ((u64)ford(bestv[i]) << 32) | (u64)(0xFFFFFFFFu - (unsigned)bestc[i]);
        atomicMax(&sbest[ty + 16 * i], key);
    }
    __syncthreads();
    if (tid < MTILE && n0 + tid < NTOK) {
        unsigned low = (unsigned)(sbest[tid] & 0xFFFFFFFFull);
        g_idx[n0 + tid] = (int)(0xFFFFFFFFu - low);
    }
}

// ---------------- gather: smem-staged, GT=16 ----------------
__global__ __launch_bounds__(256) void gather_kernel(const float* __restrict__ cb,
                                                     float* __restrict__ out) {
    extern __shared__ char gsm[];
    float* st  = reinterpret_cast<float*>(gsm);              // [GT][GROW]
    int* sidx  = reinterpret_cast<int*>(gsm + GT * GROW * 4);
    const int tid = threadIdx.x;
    const int n0  = blockIdx.x * GT;

    if (tid < GT) sidx[tid] = g_idx[n0 + tid];
    __syncthreads();

    // phase 1: stage selected codebook rows; 4 independent LDG.128 in flight
    {
        float4 v[4];
#pragma unroll
        for (int k = 0; k < 4; k++) {
            const int e   = k * 1024 + tid * 4;   // element in [tok][d]
            const int tok = e >> 8, d = e & 255;
            v[k] = *reinterpret_cast<const float4*>(cb + (size_t)sidx[tok] * DIM + d);
        }
#pragma unroll
        for (int k = 0; k < 4; k++) {
            const int e   = k * 1024 + tid * 4;
            const int tok = e >> 8, d = e & 255;
            st[tok * GROW + d + 0] = v[k].x;
            st[tok * GROW + d + 1] = v[k].y;
            st[tok * GROW + d + 2] = v[k].z;
            st[tok * GROW + d + 3] = v[k].w;
        }
    }
    __syncthreads();

    // phase 2: output-major coalesced float4 stores (4 p-quads per d-row)
    const int b  = n0 >> 10;
    const int p0 = n0 & (HW - 1);
    float* ob = out + (size_t)b * DIM * HW + p0;
#pragma unroll
    for (int k = 0; k < 4; k++) {
        const int e4 = k * 256 + tid;             // d = e4/4, p-quad = e4%4
        const int d  = e4 >> 2;
        const int p  = (e4 & 3) * 4;
        float4 v;
        v.x = st[(p + 0) * GROW + d];
        v.y = st[(p + 1) * GROW + d];
        v.z = st[(p + 2) * GROW + d];
        v.w = st[(p + 3) * GROW + d];
        *reinterpret_cast<float4*>(ob + (size_t)d * HW + p) = v;
    }
}

extern "C" void kernel_launch(void* const* d_in, const int* in_sizes, int n_in,
                              void* d_out, int out_size) {
    const float* x  = (const float*)d_in[0];
    const float* cb = (const float*)d_in[1];
    float* out = (float*)d_out;

    cudaFuncSetAttribute(sweep_kernel, cudaFuncAttributeMaxDynamicSharedMemorySize, SM_TOT);
    cudaFuncSetAttribute(gather_kernel, cudaFuncAttributeMaxDynamicSharedMemorySize, GSM_TOT);

    prep_kernel<<<KCODES / PC, 256>>>(cb);
    sweep_kernel<<<NCTA, 256, SM_TOT>>>(x);
    gather_kernel<<<NTOK / GT, 256, GSM_TOT>>>(cb, out);
}

// round 15
// speedup vs baseline: 1.0024x; 1.0024x over previous
#include <cuda_runtime.h>
#include <stdint.h>

// ============================================================================
// Exact VQ argmin via packed fp32x2 FMA (SASS FFMA2, 2 MAC/instr).
// R15 = best-of composition: R14 prep (PC=16, 6.3us) + R12 gather (GT=32,
//       MLP=8, 9.4us) + R9-lineage sweep (untouched, at fma-issue floor).
// ============================================================================

#define NTOK   16384
#define DIM    256
#define HW     1024
#define KCODES 4096
#define MTILE  112
#define NCTA   147              // ceil(16384/112)
#define CTILE  256              // codes per tile
#define DC     32               // dims per chunk
#define NCHUNK ((KCODES / CTILE) * (DIM / DC))   // 16 * 8 = 128
#define BSTG   32768            // one B stage: 32 d x 1024B

// sweep smem (bytes)
#define SM_A    0                 // 256 d x 112 tok x 4B = 114688
#define SM_B    114688            // 3 x 32768 = 98304
#define SM_Q    212992            // csqh 4096 f32 = 16384
#define SM_BEST 229376            // 112 u64 (+pad)
#define SM_TOT  230400

// gather (R12 parameters)
#define GT      32                // tokens per gather CTA
#define GROW    257               // padded row stride (floats)
#define GSM_TOT (GT * GROW * 4 + 256)

// prep (R14 parameters)
#define PC      16                // codes per prep CTA

__device__ float g_cbT[DIM * KCODES];   // [d][code]
__device__ float g_csqh[KCODES];        // -0.5*||c||^2
__device__ int   g_idx[NTOK];

typedef unsigned long long u64;
__device__ __forceinline__ uint32_t smem_u32(const void* p) {
    uint32_t a;
    asm("{ .reg .u64 t; cvta.to.shared.u64 t, %1; cvt.u32.u64 %0, t; }" : "=r"(a) : "l"(p));
    return a;
}
__device__ __forceinline__ unsigned ford(float f) {
    unsigned u = __float_as_uint(f);
    return (u & 0x80000000u) ? ~u : (u | 0x80000000u);
}
__device__ __forceinline__ u64 pack2(float v) {
    u64 r; unsigned b = __float_as_uint(v);
    asm("mov.b64 %0, {%1, %1};" : "=l"(r) : "r"(b));
    return r;
}
__device__ __forceinline__ void fma2(u64& acc, u64 a, u64 b) {
    asm("fma.rn.f32x2 %0, %1, %2, %0;" : "+l"(acc) : "l"(a), "l"(b));
}
__device__ __forceinline__ void lds_v2u64(u64& r0, u64& r1, uint32_t a) {
    asm volatile("ld.shared.v2.u64 {%0,%1}, [%2];" : "=l"(r0), "=l"(r1) : "r"(a));
}
#define CP16(d, s)  asm volatile("cp.async.cg.shared.global [%0], [%1], 16;" :: "r"(d), "l"(s))
#define CPCOMMIT()  asm volatile("cp.async.commit_group;" ::: "memory")
#define CPWAIT1()   asm volatile("cp.async.wait_group 1;" ::: "memory")
#define CPWAIT0()   asm volatile("cp.async.wait_group 0;" ::: "memory")

// ---------------- fused prep: transpose + csqh, 16 codes/CTA (R14) ---------
__global__ __launch_bounds__(256) void prep_kernel(const float* __restrict__ cb) {
    __shared__ float t[PC * GROW];            // [code][d], stride 257
    const int tid  = threadIdx.x;
    const int code = tid >> 4;                // 0..15
    const int seg  = tid & 15;                // 16-dim segment
    const int c0   = blockIdx.x * PC;

    const float* row = cb + (size_t)(c0 + code) * DIM + seg * 16;
    float sq = 0.f;
#pragma unroll
    for (int i = 0; i < 4; i++) {
        float4 v = reinterpret_cast<const float4*>(row)[i];
        sq = fmaf(v.x, v.x, sq); sq = fmaf(v.y, v.y, sq);
        sq = fmaf(v.z, v.z, sq); sq = fmaf(v.w, v.w, sq);
        const int d = seg * 16 + i * 4;
        t[code * GROW + d + 0] = v.x;
        t[code * GROW + d + 1] = v.y;
        t[code * GROW + d + 2] = v.z;
        t[code * GROW + d + 3] = v.w;
    }
#pragma unroll
    for (int o = 8; o > 0; o >>= 1) sq += __shfl_xor_sync(0xFFFFFFFFu, sq, o);
    if (seg == 0) g_csqh[c0 + code] = -0.5f * sq;
    __syncthreads();

#pragma unroll
    for (int k = 0; k < 16; k++) {
        const int d  = k * 16 + (tid >> 4);
        const int cc = tid & 15;
        g_cbT[(size_t)d * KCODES + c0 + cc] = t[cc * GROW + d];
    }
}

// B chunk prefetch: chunk index cc -> stage cc%3
__device__ __forceinline__ void prefetch_chunk(uint32_t sb, int cc, int tid) {
    const int ct = cc >> 3, dcc = cc & 7;
    const char* src = reinterpret_cast<const char*>(
        g_cbT + (size_t)(dcc * DC) * KCODES + ct * CTILE);
    const uint32_t dst = sb + SM_B + (cc % 3) * BSTG;
#pragma unroll
    for (int k = 0; k < 8; k++) {
        int s = tid + k * 256;                 // 2048 x 16B
        int r = s >> 6, c = s & 63;
        CP16(dst + r * 1024 + c * 16, src + (size_t)r * (KCODES * 4) + c * 16);
    }
    CPCOMMIT();
}

// ---------------- main sweep (R9 lineage, unchanged) ----------------
__global__ __launch_bounds__(256, 1) void sweep_kernel(const float* __restrict__ x) {
    extern __shared__ char sm[];
    float* Af     = reinterpret_cast<float*>(sm + SM_A);   // [d][112]
    float* csqh_s = reinterpret_cast<float*>(sm + SM_Q);
    u64*   sbest  = reinterpret_cast<u64*>(sm + SM_BEST);
    const uint32_t sb = smem_u32(sm);

    const int tid = threadIdx.x;
    const int tx  = tid & 15;       // code group (codes tx*4 + s*64 + q*2 .. +1)
    const int ty  = tid >> 4;       // token slot: tokens ty + 16*m, m<7
    const int n0  = blockIdx.x * MTILE;

    // ---- A fill: one d-row per thread, 28 x 16B cp.async, batch-split ----
    {
        const int pos0 = n0 & (HW - 1);
        const int b0   = n0 >> 10;
        const int len1 = min(MTILE, HW - pos0);          // multiple of 16
        const int d    = tid;
        const uint32_t dst = sb + SM_A + d * (MTILE * 4);
#pragma unroll
        for (int c = 0; c < 28; c++) {
            const int col0 = c * 4;                      // 4 tokens = 16 bytes
            if (col0 < len1) {
                const float* src = x + ((size_t)b0 * DIM + d) * HW + pos0 + col0;
                CP16(dst + col0 * 4, src);
            } else if (b0 + 1 < 16) {
                const float* src = x + ((size_t)(b0 + 1) * DIM + d) * HW + (col0 - len1);
                CP16(dst + col0 * 4, src);
            }
        }
        CPCOMMIT();
    }
    for (int i = tid; i < KCODES; i += 256) csqh_s[i] = g_csqh[i];
    if (tid < MTILE) sbest[tid] = 0ull;
    // ---- B prologue: chunks 0 and 1 ----
    prefetch_chunk(sb, 0, tid);
    prefetch_chunk(sb, 1, tid);

    float bestv[7];
    int   bestc[7];
#pragma unroll
    for (int i = 0; i < 7; i++) { bestv[i] = -3.4e38f; bestc[i] = 0; }

    u64 acc[7][8];

    for (int cidx = 0; cidx < NCHUNK; cidx++) {
        const int ct  = cidx >> 3;
        const int dcc = cidx & 7;

        // wait for chunk cidx (leave next in flight); single barrier makes
        // chunk cidx visible AND proves all warps finished cidx-1, whose
        // stage (cidx+2)%3 we are about to overwrite.
        if (cidx + 1 < NCHUNK) CPWAIT1(); else CPWAIT0();
        __syncthreads();
        if (cidx + 2 < NCHUNK) prefetch_chunk(sb, cidx + 2, tid);

        // acc init at tile start: -0.5*||c||^2 pairs (codes tx*4 + s*64 + q*2)
        if (dcc == 0) {
            const int qb = ct * CTILE + tx * 4;
            u64 k8[8];
#pragma unroll
            for (int s = 0; s < 4; s++) {
                k8[s * 2]     = *reinterpret_cast<const u64*>(csqh_s + qb + s * 64);
                k8[s * 2 + 1] = *reinterpret_cast<const u64*>(csqh_s + qb + s * 64 + 2);
            }
#pragma unroll
            for (int i = 0; i < 7; i++)
#pragma unroll
                for (int j = 0; j < 8; j++) acc[i][j] = k8[j];
        }

        // ---- compute 32 d-steps ----
        const float*   Abase = Af + dcc * DC * MTILE + ty;
        const uint32_t Bbase = sb + SM_B + (cidx % 3) * BSTG + tx * 16;
#pragma unroll 4
        for (int k = 0; k < DC; k++) {
            u64 pa[7];
#pragma unroll
            for (int m = 0; m < 7; m++)
                pa[m] = pack2(Abase[k * MTILE + 16 * m]);
            u64 bb[8];
#pragma unroll
            for (int s = 0; s < 4; s++)
                lds_v2u64(bb[s * 2], bb[s * 2 + 1], Bbase + k * 1024 + s * 256);
#pragma unroll
            for (int i = 0; i < 7; i++)
#pragma unroll
                for (int j = 0; j < 8; j++)
                    fma2(acc[i][j], pa[i], bb[j]);
        }

        // ---- tile epilogue: running argmax ----
        if (dcc == 7) {
            const int cb0 = ct * CTILE + tx * 4;
#pragma unroll
            for (int i = 0; i < 7; i++)
#pragma unroll
                for (int s = 0; s < 4; s++)
#pragma unroll
                    for (int q = 0; q < 2; q++) {
                        unsigned lo, hi;
                        asm("mov.b64 {%0,%1}, %2;" : "=r"(lo), "=r"(hi) : "l"(acc[i][s * 2 + q]));
                        float v0 = __uint_as_float(lo), v1 = __uint_as_float(hi);
                        int c = cb0 + s * 64 + q * 2;
                        if (v0 > bestv[i]) { bestv[i] = v0; bestc[i] = c; }
                        if (v1 > bestv[i]) { bestv[i] = v1; bestc[i] = c + 1; }
                    }
        }
    }

    // ---- cross-thread reduction: max value, then min code ----
#pragma unroll
    for (int i = 0; i < 7; i++) {
        u64 key = ((u64)ford(bestv[i]) << 32) | (u64)(0xFFFFFFFFu - (unsigned)bestc[i]);
        atomicMax(&sbest[ty + 16 * i], key);
    }
    __syncthreads();
    if (tid < MTILE && n0 + tid < NTOK) {
        unsigned low = (unsigned)(sbest[tid] & 0xFFFFFFFFull);
        g_idx[n0 + tid] = (int)(0xFFFFFFFFu - low);
    }
}

// ---------------- gather: smem-staged, GT=32, MLP=8 (R12) ----------------
__global__ __launch_bounds__(256) void gather_kernel(const float* __restrict__ cb,
                                                     float* __restrict__ out) {
    extern __shared__ char gsm[];
    float* st  = reinterpret_cast<float*>(gsm);              // [GT][GROW]
    int* sidx  = reinterpret_cast<int*>(gsm + GT * GROW * 4);
    const int tid = threadIdx.x;
    const int n0  = blockIdx.x * GT;

    if (tid < GT) sidx[tid] = g_idx[n0 + tid];
    __syncthreads();

    // phase 1: stage selected codebook rows; 8 independent LDG.128 in flight
    {
        float4 v[8];
#pragma unroll
        for (int k = 0; k < 8; k++) {
            const int e   = k * 1024 + tid * 4;   // element in [tok][d]
            const int tok = e >> 8, d = e & 255;
            v[k] = *reinterpret_cast<const float4*>(cb + (size_t)sidx[tok] * DIM + d);
        }
#pragma unroll
        for (int k = 0; k < 8; k++) {
            const int e   = k * 1024 + tid * 4;
            const int tok = e >> 8, d = e & 255;
            st[tok * GROW + d + 0] = v[k].x;
            st[tok * GROW + d + 1] = v[k].y;
            st[tok * GROW + d + 2] = v[k].z;
            st[tok * GROW + d + 3] = v[k].w;
        }
    }
    __syncthreads();

    // phase 2: output-major coalesced float4 stores (8 p-quads per d-row)
    const int b  = n0 >> 10;
    const int p0 = n0 & (HW - 1);
    float* ob = out + (size_t)b * DIM * HW + p0;
#pragma unroll
    for (int k = 0; k < 8; k++) {
        const int e4 = k * 256 + tid;             // d = e4/8, p-quad = e4%8
        const int d  = e4 >> 3;
        const int p  = (e4 & 7) * 4;
        float4 v;
        v.x = st[(p + 0) * GROW + d];
        v.y = st[(p + 1) * GROW + d];
        v.z = st[(p + 2) * GROW + d];
        v.w = st[(p + 3) * GROW + d];
        *reinterpret_cast<float4*>(ob + (size_t)d * HW + p) = v;
    }
}

extern "C" void kernel_launch(void* const* d_in, const int* in_sizes, int n_in,
                              void* d_out, int out_size) {
    const float* x  = (const float*)d_in[0];
    const float* cb = (const float*)d_in[1];
    float* out = (float*)d_out;

    cudaFuncSetAttribute(sweep_kernel, cudaFuncAttributeMaxDynamicSharedMemorySize, SM_TOT);
    cudaFuncSetAttribute(gather_kernel, cudaFuncAttributeMaxDynamicSharedMemorySize, GSM_TOT);

    prep_kernel<<<KCODES / PC, 256>>>(cb);
    sweep_kernel<<<NCTA, 256, SM_TOT>>>(x);
    gather_kernel<<<NTOK / GT, 256, GSM_TOT>>>(cb, out);
}

// round 16
// speedup vs baseline: 1.0080x; 1.0056x over previous
#include <cuda_runtime.h>
#include <stdint.h>

// ============================================================================
// Exact VQ argmin via packed fp32x2 FMA (SASS FFMA2, 2 MAC/instr).
// R16 = R15 best-of (R14 prep PC=16, R12 gather GT=32/MLP=8, R9 sweep) with
//       the sweep's final reduction switched from smem atomicMax to an
//       in-register shfl butterfly over the 16 consecutive lanes per token.
// ============================================================================

#define NTOK   16384
#define DIM    256
#define HW     1024
#define KCODES 4096
#define MTILE  112
#define NCTA   147              // ceil(16384/112)
#define CTILE  256              // codes per tile
#define DC     32               // dims per chunk
#define NCHUNK ((KCODES / CTILE) * (DIM / DC))   // 16 * 8 = 128
#define BSTG   32768            // one B stage: 32 d x 1024B

// sweep smem (bytes)
#define SM_A    0                 // 256 d x 112 tok x 4B = 114688
#define SM_B    114688            // 3 x 32768 = 98304
#define SM_Q    212992            // csqh 4096 f32 = 16384
#define SM_TOT  229376

// gather (R12 parameters)
#define GT      32                // tokens per gather CTA
#define GROW    257               // padded row stride (floats)
#define GSM_TOT (GT * GROW * 4 + 256)

// prep (R14 parameters)
#define PC      16                // codes per prep CTA

__device__ float g_cbT[DIM * KCODES];   // [d][code]
__device__ float g_csqh[KCODES];        // -0.5*||c||^2
__device__ int   g_idx[NTOK];

typedef unsigned long long u64;
__device__ __forceinline__ uint32_t smem_u32(const void* p) {
    uint32_t a;
    asm("{ .reg .u64 t; cvta.to.shared.u64 t, %1; cvt.u32.u64 %0, t; }" : "=r"(a) : "l"(p));
    return a;
}
__device__ __forceinline__ unsigned ford(float f) {
    unsigned u = __float_as_uint(f);
    return (u & 0x80000000u) ? ~u : (u | 0x80000000u);
}
__device__ __forceinline__ u64 pack2(float v) {
    u64 r; unsigned b = __float_as_uint(v);
    asm("mov.b64 %0, {%1, %1};" : "=l"(r) : "r"(b));
    return r;
}
__device__ __forceinline__ void fma2(u64& acc, u64 a, u64 b) {
    asm("fma.rn.f32x2 %0, %1, %2, %0;" : "+l"(acc) : "l"(a), "l"(b));
}
__device__ __forceinline__ void lds_v2u64(u64& r0, u64& r1, uint32_t a) {
    asm volatile("ld.shared.v2.u64 {%0,%1}, [%2];" : "=l"(r0), "=l"(r1) : "r"(a));
}
#define CP16(d, s)  asm volatile("cp.async.cg.shared.global [%0], [%1], 16;" :: "r"(d), "l"(s))
#define CPCOMMIT()  asm volatile("cp.async.commit_group;" ::: "memory")
#define CPWAIT1()   asm volatile("cp.async.wait_group 1;" ::: "memory")
#define CPWAIT0()   asm volatile("cp.async.wait_group 0;" ::: "memory")

// ---------------- fused prep: transpose + csqh, 16 codes/CTA (R14) ---------
__global__ __launch_bounds__(256) void prep_kernel(const float* __restrict__ cb) {
    __shared__ float t[PC * GROW];            // [code][d], stride 257
    const int tid  = threadIdx.x;
    const int code = tid >> 4;                // 0..15
    const int seg  = tid & 15;                // 16-dim segment
    const int c0   = blockIdx.x * PC;

    const float* row = cb + (size_t)(c0 + code) * DIM + seg * 16;
    float sq = 0.f;
#pragma unroll
    for (int i = 0; i < 4; i++) {
        float4 v = reinterpret_cast<const float4*>(row)[i];
        sq = fmaf(v.x, v.x, sq); sq = fmaf(v.y, v.y, sq);
        sq = fmaf(v.z, v.z, sq); sq = fmaf(v.w, v.w, sq);
        const int d = seg * 16 + i * 4;
        t[code * GROW + d + 0] = v.x;
        t[code * GROW + d + 1] = v.y;
        t[code * GROW + d + 2] = v.z;
        t[code * GROW + d + 3] = v.w;
    }
#pragma unroll
    for (int o = 8; o > 0; o >>= 1) sq += __shfl_xor_sync(0xFFFFFFFFu, sq, o);
    if (seg == 0) g_csqh[c0 + code] = -0.5f * sq;
    __syncthreads();

#pragma unroll
    for (int k = 0; k < 16; k++) {
        const int d  = k * 16 + (tid >> 4);
        const int cc = tid & 15;
        g_cbT[(size_t)d * KCODES + c0 + cc] = t[cc * GROW + d];
    }
}

// B chunk prefetch: chunk index cc -> stage cc%3
__device__ __forceinline__ void prefetch_chunk(uint32_t sb, int cc, int tid) {
    const int ct = cc >> 3, dcc = cc & 7;
    const char* src = reinterpret_cast<const char*>(
        g_cbT + (size_t)(dcc * DC) * KCODES + ct * CTILE);
    const uint32_t dst = sb + SM_B + (cc % 3) * BSTG;
#pragma unroll
    for (int k = 0; k < 8; k++) {
        int s = tid + k * 256;                 // 2048 x 16B
        int r = s >> 6, c = s & 63;
        CP16(dst + r * 1024 + c * 16, src + (size_t)r * (KCODES * 4) + c * 16);
    }
    CPCOMMIT();
}

// ---------------- main sweep ----------------
__global__ __launch_bounds__(256, 1) void sweep_kernel(const float* __restrict__ x) {
    extern __shared__ char sm[];
    float* Af     = reinterpret_cast<float*>(sm + SM_A);   // [d][112]
    float* csqh_s = reinterpret_cast<float*>(sm + SM_Q);
    const uint32_t sb = smem_u32(sm);

    const int tid = threadIdx.x;
    const int tx  = tid & 15;       // code group (codes tx*4 + s*64 + q*2 .. +1)
    const int ty  = tid >> 4;       // token slot: tokens ty + 16*m, m<7
    const int n0  = blockIdx.x * MTILE;

    // ---- A fill: one d-row per thread, 28 x 16B cp.async, batch-split ----
    {
        const int pos0 = n0 & (HW - 1);
        const int b0   = n0 >> 10;
        const int len1 = min(MTILE, HW - pos0);          // multiple of 16
        const int d    = tid;
        const uint32_t dst = sb + SM_A + d * (MTILE * 4);
#pragma unroll
        for (int c = 0; c < 28; c++) {
            const int col0 = c * 4;                      // 4 tokens = 16 bytes
            if (col0 < len1) {
                const float* src = x + ((size_t)b0 * DIM + d) * HW + pos0 + col0;
                CP16(dst + col0 * 4, src);
            } else if (b0 + 1 < 16) {
                const float* src = x + ((size_t)(b0 + 1) * DIM + d) * HW + (col0 - len1);
                CP16(dst + col0 * 4, src);
            }
        }
        CPCOMMIT();
    }
    for (int i = tid; i < KCODES; i += 256) csqh_s[i] = g_csqh[i];
    // ---- B prologue: chunks 0 and 1 ----
    prefetch_chunk(sb, 0, tid);
    prefetch_chunk(sb, 1, tid);

    float bestv[7];
    int   bestc[7];
#pragma unroll
    for (int i = 0; i < 7; i++) { bestv[i] = -3.4e38f; bestc[i] = 0; }

    u64 acc[7][8];

    for (int cidx = 0; cidx < NCHUNK; cidx++) {
        const int ct  = cidx >> 3;
        const int dcc = cidx & 7;

        // wait for chunk cidx (leave next in flight); single barrier makes
        // chunk cidx visible AND proves all warps finished cidx-1, whose
        // stage (cidx+2)%3 we are about to overwrite.
        if (cidx + 1 < NCHUNK) CPWAIT1(); else CPWAIT0();
        __syncthreads();
        if (cidx + 2 < NCHUNK) prefetch_chunk(sb, cidx + 2, tid);

        // acc init at tile start: -0.5*||c||^2 pairs (codes tx*4 + s*64 + q*2)
        if (dcc == 0) {
            const int qb = ct * CTILE + tx * 4;
            u64 k8[8];
#pragma unroll
            for (int s = 0; s < 4; s++) {
                k8[s * 2]     = *reinterpret_cast<const u64*>(csqh_s + qb + s * 64);
                k8[s * 2 + 1] = *reinterpret_cast<const u64*>(csqh_s + qb + s * 64 + 2);
            }
#pragma unroll
            for (int i = 0; i < 7; i++)
#pragma unroll
                for (int j = 0; j < 8; j++) acc[i][j] = k8[j];
        }

        // ---- compute 32 d-steps ----
        const float*   Abase = Af + dcc * DC * MTILE + ty;
        const uint32_t Bbase = sb + SM_B + (cidx % 3) * BSTG + tx * 16;
#pragma unroll 4
        for (int k = 0; k < DC; k++) {
            u64 pa[7];
#pragma unroll
            for (int m = 0; m < 7; m++)
                pa[m] = pack2(Abase[k * MTILE + 16 * m]);
            u64 bb[8];
#pragma unroll
            for (int s = 0; s < 4; s++)
                lds_v2u64(bb[s * 2], bb[s * 2 + 1], Bbase + k * 1024 + s * 256);
#pragma unroll
            for (int i = 0; i < 7; i++)
#pragma unroll
                for (int j = 0; j < 8; j++)
                    fma2(acc[i][j], pa[i], bb[j]);
        }

        // ---- tile epilogue: running argmax ----
        if (dcc == 7) {
            const int cb0 = ct * CTILE + tx * 4;
#pragma unroll
            for (int i = 0; i < 7; i++)
#pragma unroll
                for (int s = 0; s < 4; s++)
#pragma unroll
                    for (int q = 0; q < 2; q++) {
                        unsigned lo, hi;
                        asm("mov.b64 {%0,%1}, %2;" : "=r"(lo), "=r"(hi) : "l"(acc[i][s * 2 + q]));
                        float v0 = __uint_as_float(lo), v1 = __uint_as_float(hi);
                        int c = cb0 + s * 64 + q * 2;
                        if (v0 > bestv[i]) { bestv[i] = v0; bestc[i] = c; }
                        if (v1 > bestv[i]) { bestv[i] = v1; bestc[i] = c + 1; }
                    }
        }
    }

    // ---- reduction: 16 consecutive lanes per token, shfl butterfly ----
    // key = (ford(best value) << 32) | ~code : max key == max value, then
    // min code on ties. Lanes ty*16.. share a half-warp (tx = lane & 15).
#pragma unroll
    for (int i = 0; i < 7; i++) {
        unsigned kh = ford(bestv[i]);
        unsigned kl = 0xFFFFFFFFu - (unsigned)bestc[i];
#pragma unroll
        for (int o = 1; o < 16; o <<= 1) {
            unsigned oh = __shfl_xor_sync(0xFFFFFFFFu, kh, o);
            unsigned ol = __shfl_xor_sync(0xFFFFFFFFu, kl, o);
            if (oh > kh || (oh == kh && ol > kl)) { kh = oh; kl = ol; }
        }
        if (tx == 0) {
            const int n = n0 + ty + 16 * i;
            if (n < NTOK) g_idx[n] = (int)(0xFFFFFFFFu - kl);
        }
    }
}

// ---------------- gather: smem-staged, GT=32, MLP=8 (R12) ----------------
__global__ __launch_bounds__(256) void gather_kernel(const float* __restrict__ cb,
                                                     float* __restrict__ out) {
    extern __shared__ char gsm[];
    float* st  = reinterpret_cast<float*>(gsm);              // [GT][GROW]
    int* sidx  = reinterpret_cast<int*>(gsm + GT * GROW * 4);
    const int tid = threadIdx.x;
    const int n0  = blockIdx.x * GT;

    if (tid < GT) sidx[tid] = g_idx[n0 + tid];
    __syncthreads();

    // phase 1: stage selected codebook rows; 8 independent LDG.128 in flight
    {
        float4 v[8];
#pragma unroll
        for (int k = 0; k < 8; k++) {
            const int e   = k * 1024 + tid * 4;   // element in [tok][d]
            const int tok = e >> 8, d = e & 255;
            v[k] = *reinterpret_cast<const float4*>(cb + (size_t)sidx[tok] * DIM + d);
        }
#pragma unroll
        for (int k = 0; k < 8; k++) {
            const int e   = k * 1024 + tid * 4;
            const int tok = e >> 8, d = e & 255;
            st[tok * GROW + d + 0] = v[k].x;
            st[tok * GROW + d + 1] = v[k].y;
            st[tok * GROW + d + 2] = v[k].z;
            st[tok * GROW + d + 3] = v[k].w;
        }
    }
    __syncthreads();

    // phase 2: output-major coalesced float4 stores (8 p-quads per d-row)
    const int b  = n0 >> 10;
    const int p0 = n0 & (HW - 1);
    float* ob = out + (size_t)b * DIM * HW + p0;
#pragma unroll
    for (int k = 0; k < 8; k++) {
        const int e4 = k * 256 + tid;             // d = e4/8, p-quad = e4%8
        const int d  = e4 >> 3;
        const int p  = (e4 & 7) * 4;
        float4 v;
        v.x = st[(p + 0) * GROW + d];
        v.y = st[(p + 1) * GROW + d];
        v.z = st[(p + 2) * GROW + d];
        v.w = st[(p + 3) * GROW + d];
        *reinterpret_cast<float4*>(ob + (size_t)d * HW + p) = v;
    }
}

extern "C" void kernel_launch(void* const* d_in, const int* in_sizes, int n_in,
                              void* d_out, int out_size) {
    const float* x  = (const float*)d_in[0];
    const float* cb = (const float*)d_in[1];
    float* out = (float*)d_out;

    cudaFuncSetAttribute(sweep_kernel, cudaFuncAttributeMaxDynamicSharedMemorySize, SM_TOT);
    cudaFuncSetAttribute(gather_kernel, cudaFuncAttributeMaxDynamicSharedMemorySize, GSM_TOT);

    prep_kernel<<<KCODES / PC, 256>>>(cb);
    sweep_kernel<<<NCTA, 256, SM_TOT>>>(x);
    gather_kernel<<<NTOK / GT, 256, GSM_TOT>>>(cb, out);
}